// round 10
// baseline (speedup 1.0000x reference)
#include <cuda_runtime.h>
#include <cuda_bf16.h>
#include <stdint.h>

// Problem shape (fixed): idx [B=4, T=4096, E=1024], W* [E, H=64], b* [H]
// out [B, T, H] fp32.
// Math: out = (Q K^T / sqrt(E)) V == Q (K^T V) / 32  (no softmax/mask in ref)
//
// sm_103 (no 'a') PTX target: tcgen05 unavailable; tensor cores via legacy
// mma.sync.m16n8k16.bf16 with fp32->bf16 hi/lo split:
//   C = Ahi*Whi + Ahi*Wlo + Alo*Whi   (lo*lo dropped, ~2^-17 relative)

#define BB 4
#define TT 4096
#define EE 1024
#define HH 64
#define ROWS (BB * TT)          // 16384
#define SPLITS 64
#define CHUNK (TT / SPLITS)     // 64

__device__ float g_Q[ROWS * HH];
__device__ float g_K[ROWS * HH];
__device__ float g_V[ROWS * HH];
__device__ float g_Mpart[BB * SPLITS * HH * HH];
__device__ float g_M[BB * HH * HH];
__device__ __nv_bfloat16 g_Whi[3 * HH * EE];
__device__ __nv_bfloat16 g_Wlo[3 * HH * EE];

#define SW128(off) ((off) ^ (((off) >> 3) & 0x70))

__device__ __forceinline__ uint32_t s2u(const void* p) {
    return (uint32_t)__cvta_generic_to_shared(p);
}

__device__ __forceinline__ void ldsm_x4(uint32_t& r0, uint32_t& r1,
                                        uint32_t& r2, uint32_t& r3, uint32_t a) {
    asm volatile("ldmatrix.sync.aligned.m8n8.x4.shared.b16 {%0,%1,%2,%3}, [%4];"
                 : "=r"(r0), "=r"(r1), "=r"(r2), "=r"(r3) : "r"(a));
}

__device__ __forceinline__ void mma16816(float* c, const uint32_t* a,
                                         const uint32_t* b) {
    asm volatile(
        "mma.sync.aligned.m16n8k16.row.col.f32.bf16.bf16.f32 "
        "{%0,%1,%2,%3}, {%4,%5,%6,%7}, {%8,%9}, {%0,%1,%2,%3};"
        : "+f"(c[0]), "+f"(c[1]), "+f"(c[2]), "+f"(c[3])
        : "r"(a[0]), "r"(a[1]), "r"(a[2]), "r"(a[3]), "r"(b[0]), "r"(b[1]));
}

__device__ __forceinline__ void cp16(uint32_t dst, const void* src) {
    asm volatile("cp.async.cg.shared.global [%0], [%1], 16;"
                 :: "r"(dst), "l"(__cvta_generic_to_global(src)) : "memory");
}
__device__ __forceinline__ void cp_commit() {
    asm volatile("cp.async.commit_group;" ::: "memory");
}
__device__ __forceinline__ void cp_wait0() {
    asm volatile("cp.async.wait_group 0;" ::: "memory");
}

__device__ __forceinline__ uint32_t pack_bf16(float a, float b) {
    __nv_bfloat162 h = __floats2bfloat162_rn(a, b);
    return *reinterpret_cast<uint32_t*>(&h);
}

// ---------------------------------------------------------------------------
// Kernel 0: W conversion (coalesced transpose, hi/lo split). Grid 48 x 256.
// ---------------------------------------------------------------------------
__global__ __launch_bounds__(256) void wconv_kernel(
    const float* __restrict__ Wq, const float* __restrict__ Wk,
    const float* __restrict__ Wv)
{
    const int which = blockIdx.x >> 4;
    const int kseg  = blockIdx.x & 15;
    const int k0    = kseg * 64;
    const float* W = (which == 0) ? Wq : (which == 1) ? Wk : Wv;

    __shared__ float s[64][65];

    const int tid = threadIdx.x;
#pragma unroll
    for (int it = 0; it < 4; it++) {
        int j  = tid + it * 256;
        int r  = j >> 4;
        int c4 = (j & 15) * 4;
        float4 v = *(const float4*)(W + (size_t)(k0 + r) * HH + c4);
        s[r][c4 + 0] = v.x; s[r][c4 + 1] = v.y;
        s[r][c4 + 2] = v.z; s[r][c4 + 3] = v.w;
    }
    __syncthreads();

#pragma unroll
    for (int it = 0; it < 2; it++) {
        int id = tid + it * 256;
        int n  = id >> 3;
        int kg = (id & 7) * 8;
        float x[8], h[8];
#pragma unroll
        for (int j = 0; j < 8; j++) {
            x[j] = s[kg + j][n];
            __nv_bfloat16 hb = __float2bfloat16(x[j]);
            h[j] = __bfloat162float(hb);
        }
        uint4 hp, lp;
        hp.x = pack_bf16(x[0], x[1]); hp.y = pack_bf16(x[2], x[3]);
        hp.z = pack_bf16(x[4], x[5]); hp.w = pack_bf16(x[6], x[7]);
        lp.x = pack_bf16(x[0] - h[0], x[1] - h[1]);
        lp.y = pack_bf16(x[2] - h[2], x[3] - h[3]);
        lp.z = pack_bf16(x[4] - h[4], x[5] - h[5]);
        lp.w = pack_bf16(x[6] - h[6], x[7] - h[7]);
        size_t off = (size_t)(which * 64 + n) * EE + k0 + kg;
        *(uint4*)(g_Whi + off) = hp;
        *(uint4*)(g_Wlo + off) = lp;
    }
}

// ---------------------------------------------------------------------------
// Kernel 1 (v2): QKV via mma.sync bf16 hi/lo. 512 threads / 16 warps.
// CTA tile M=128 x N=192, K in 16 chunks of 64. Warp tile 32x48
// (wy: 4 M-quarters, wx: 4 N-groups). Lower reg pressure, 2x warps/SMSP.
// ---------------------------------------------------------------------------
#define SM_AHI 0
#define SM_ALO 32768
#define SM_WHI 65536
#define SM_WLO 114688
#define SMEM_TOTAL 163840

__global__ __launch_bounds__(512, 1)
void qkv_mma_kernel(const float* __restrict__ idx,
                    const float* __restrict__ bq,
                    const float* __restrict__ bk,
                    const float* __restrict__ bv)
{
    extern __shared__ char smem[];
    const uint32_t sb = s2u(smem);
    const int tid  = threadIdx.x;
    const int lane = tid & 31;
    const int wid  = tid >> 5;
    const int wy   = wid & 3;       // M quarter: rows wy*32..+31
    const int wx   = wid >> 2;      // N group:   cols wx*48..+47
    const int row0 = blockIdx.x * 128;

    const int a_m  = lane & 15;
    const int a_k8 = (lane >> 4) * 8;
    const int b_n  = (lane & 7) + ((lane >> 4) << 3);
    const int b_k8 = ((lane >> 3) & 1) * 8;

    float acc[2][6][4];
#pragma unroll
    for (int i = 0; i < 2; i++)
#pragma unroll
        for (int j = 0; j < 6; j++)
#pragma unroll
            for (int e = 0; e < 4; e++) acc[i][j][e] = 0.0f;

    float4 st[4];   // A staging (chunk c+1): 2048 f4 / 512 thr

    auto ldg_A = [&](int c) {
        const float* src = idx + (size_t)row0 * EE + c * 64;
#pragma unroll
        for (int i = 0; i < 4; i++) {
            int f4 = tid + i * 512;
            int r  = f4 >> 4;
            int cg = (f4 & 15) * 4;
            st[i] = *(const float4*)(src + (size_t)r * EE + cg);
        }
    };

    auto sts_A = [&](int buf) {
        char* aHi = smem + SM_AHI + buf * 16384;
        char* aLo = smem + SM_ALO + buf * 16384;
#pragma unroll
        for (int i = 0; i < 4; i++) {
            int f4 = tid + i * 512;
            int r  = f4 >> 4;
            int cg = (f4 & 15) * 4;
            float4 v = st[i];
            __nv_bfloat162 h01 = __floats2bfloat162_rn(v.x, v.y);
            __nv_bfloat162 h23 = __floats2bfloat162_rn(v.z, v.w);
            float2 f01 = __bfloat1622float2(h01);
            float2 f23 = __bfloat1622float2(h23);
            __nv_bfloat162 l01 = __floats2bfloat162_rn(v.x - f01.x, v.y - f01.y);
            __nv_bfloat162 l23 = __floats2bfloat162_rn(v.z - f23.x, v.w - f23.y);
            uint32_t off = SW128((uint32_t)(r * 128 + cg * 2));
            uint2 hp, lp;
            hp.x = *reinterpret_cast<uint32_t*>(&h01);
            hp.y = *reinterpret_cast<uint32_t*>(&h23);
            lp.x = *reinterpret_cast<uint32_t*>(&l01);
            lp.y = *reinterpret_cast<uint32_t*>(&l23);
            *(uint2*)(aHi + off) = hp;
            *(uint2*)(aLo + off) = lp;
        }
    };

    auto cpw = [&](int c, int buf) {
        const int k0 = c * 64;
#pragma unroll
        for (int i = 0; i < 6; i++) {
            int id  = tid + i * 512;       // 0..3071
            int sel = id >= 1536;
            int v   = id - sel * 1536;
            int n   = v >> 3;
            int ku  = v & 7;
            const __nv_bfloat16* src =
                (sel ? g_Wlo : g_Whi) + (size_t)n * EE + k0 + ku * 8;
            uint32_t dst = sb + (sel ? SM_WLO : SM_WHI) + buf * 24576
                         + SW128((uint32_t)(n * 128 + ku * 16));
            cp16(dst, src);
        }
        cp_commit();
    };

    auto compute = [&](int buf) {
        const uint32_t aHiB = sb + SM_AHI + buf * 16384;
        const uint32_t aLoB = sb + SM_ALO + buf * 16384;
        const uint32_t wHiB = sb + SM_WHI + buf * 24576;
        const uint32_t wLoB = sb + SM_WLO + buf * 24576;
#pragma unroll
        for (int ks = 0; ks < 4; ks++) {
            uint32_t aH[2][4], aL[2][4], bH[3][4], bL[3][4];
            const uint32_t akoff = (uint32_t)((ks * 16 + a_k8) * 2);
            const uint32_t bkoff = (uint32_t)((ks * 16 + b_k8) * 2);
#pragma unroll
            for (int mi = 0; mi < 2; mi++) {
                uint32_t roff = (uint32_t)((wy * 32 + mi * 16 + a_m) * 128);
                ldsm_x4(aH[mi][0], aH[mi][1], aH[mi][2], aH[mi][3],
                        aHiB + SW128(roff + akoff));
                ldsm_x4(aL[mi][0], aL[mi][1], aL[mi][2], aL[mi][3],
                        aLoB + SW128(roff + akoff));
            }
#pragma unroll
            for (int jj = 0; jj < 3; jj++) {
                uint32_t noff = (uint32_t)((wx * 48 + jj * 16 + b_n) * 128);
                ldsm_x4(bH[jj][0], bH[jj][1], bH[jj][2], bH[jj][3],
                        wHiB + SW128(noff + bkoff));
                ldsm_x4(bL[jj][0], bL[jj][1], bL[jj][2], bL[jj][3],
                        wLoB + SW128(noff + bkoff));
            }
            // hi*hi
#pragma unroll
            for (int mi = 0; mi < 2; mi++)
#pragma unroll
                for (int jj = 0; jj < 3; jj++) {
                    mma16816(acc[mi][jj * 2 + 0], aH[mi], &bH[jj][0]);
                    mma16816(acc[mi][jj * 2 + 1], aH[mi], &bH[jj][2]);
                }
            // hi*lo
#pragma unroll
            for (int mi = 0; mi < 2; mi++)
#pragma unroll
                for (int jj = 0; jj < 3; jj++) {
                    mma16816(acc[mi][jj * 2 + 0], aH[mi], &bL[jj][0]);
                    mma16816(acc[mi][jj * 2 + 1], aH[mi], &bL[jj][2]);
                }
            // lo*hi
#pragma unroll
            for (int mi = 0; mi < 2; mi++)
#pragma unroll
                for (int jj = 0; jj < 3; jj++) {
                    mma16816(acc[mi][jj * 2 + 0], aL[mi], &bH[jj][0]);
                    mma16816(acc[mi][jj * 2 + 1], aL[mi], &bH[jj][2]);
                }
        }
    };

    ldg_A(0);
    cpw(0, 0);
    sts_A(0);
    cp_wait0();
    __syncthreads();

    for (int c = 0; c < 16; c++) {
        const int buf = c & 1;
        if (c < 15) {
            cpw(c + 1, buf ^ 1);
            ldg_A(c + 1);
        }
        compute(buf);
        if (c < 15) {
            sts_A(buf ^ 1);
            cp_wait0();
        }
        __syncthreads();
    }

    const float* const biases[3] = {bq, bk, bv};
    float* const outs[3] = {g_Q, g_K, g_V};
#pragma unroll
    for (int mi = 0; mi < 2; mi++) {
#pragma unroll
        for (int j = 0; j < 6; j++) {
            int n   = wx * 48 + j * 8 + (lane & 3) * 2;
            int t   = n >> 6;
            int col = n & 63;
            float2 bb = *(const float2*)(biases[t] + col);
            int m0 = row0 + wy * 32 + mi * 16 + (lane >> 2);
            float2 v0 = {acc[mi][j][0] + bb.x, acc[mi][j][1] + bb.y};
            float2 v1 = {acc[mi][j][2] + bb.x, acc[mi][j][3] + bb.y};
            *(float2*)(outs[t] + (size_t)m0 * HH + col) = v0;
            *(float2*)(outs[t] + (size_t)(m0 + 8) * HH + col) = v1;
        }
    }
}

// ---------------------------------------------------------------------------
// Kernel 2: partial M = K^T V over a CHUNK of T, per batch.  (unchanged)
// ---------------------------------------------------------------------------
__global__ __launch_bounds__(256) void kv_outer_kernel()
{
    const int b  = blockIdx.x;
    const int sp = blockIdx.y;
    const float* Kp = g_K + ((size_t)b * TT + (size_t)sp * CHUNK) * HH;
    const float* Vp = g_V + ((size_t)b * TT + (size_t)sp * CHUNK) * HH;

    __shared__ float Ks[CHUNK][HH];
    __shared__ float Vs[CHUNK][HH];

    const int tid = threadIdx.x;
    for (int i = tid; i < CHUNK * HH / 4; i += 256) {
        ((float4*)&Ks[0][0])[i] = ((const float4*)Kp)[i];
        ((float4*)&Vs[0][0])[i] = ((const float4*)Vp)[i];
    }
    __syncthreads();

    const int tx = tid % 16;
    const int ty = tid / 16;
    float acc[4][4];
#pragma unroll
    for (int i = 0; i < 4; i++)
#pragma unroll
        for (int j = 0; j < 4; j++) acc[i][j] = 0.0f;

    for (int s = 0; s < CHUNK; s++) {
        float4 kv = *(const float4*)&Ks[s][ty * 4];
        float4 vv = *(const float4*)&Vs[s][tx * 4];
        float ka[4] = {kv.x, kv.y, kv.z, kv.w};
        float va[4] = {vv.x, vv.y, vv.z, vv.w};
#pragma unroll
        for (int i = 0; i < 4; i++)
#pragma unroll
            for (int j = 0; j < 4; j++) acc[i][j] += ka[i] * va[j];
    }

    float* outp = g_Mpart + ((size_t)(b * SPLITS + sp)) * HH * HH;
#pragma unroll
    for (int i = 0; i < 4; i++) {
        float4 o = {acc[i][0], acc[i][1], acc[i][2], acc[i][3]};
        *(float4*)(outp + (size_t)(ty * 4 + i) * HH + tx * 4) = o;
    }
}

// ---------------------------------------------------------------------------
// Kernel 3 (v3): reduce partials -> M[b]. Grid 256 (= 4b x 64 segs of 16 f4),
// 256 thr: 16 p-groups x 4 partials each, smem combine. 4 loads/thread.
// ---------------------------------------------------------------------------
__global__ __launch_bounds__(256) void reduce_M_kernel()
{
    const int b   = blockIdx.x >> 6;
    const int seg = blockIdx.x & 63;        // 16 f4 per seg
    const int tcol = threadIdx.x & 15;      // f4 within seg
    const int pg   = threadIdx.x >> 4;      // 0..15: 4 partials each

    const float4* base = (const float4*)g_Mpart
        + (size_t)b * SPLITS * 1024 + (size_t)(pg * 4) * 1024 + seg * 16 + tcol;

    float4 s = {0.f, 0.f, 0.f, 0.f};
#pragma unroll
    for (int p = 0; p < 4; p++) {
        float4 v = base[(size_t)p * 1024];
        s.x += v.x; s.y += v.y; s.z += v.z; s.w += v.w;
    }

    __shared__ float4 red[16][16];
    red[pg][tcol] = s;
    __syncthreads();
    if (pg == 0) {
        float4 o = red[0][tcol];
#pragma unroll
        for (int g = 1; g < 16; g++) {
            float4 v = red[g][tcol];
            o.x += v.x; o.y += v.y; o.z += v.z; o.w += v.w;
        }
        ((float4*)g_M)[(size_t)b * 1024 + seg * 16 + tcol] = o;
    }
}

// ---------------------------------------------------------------------------
// Kernel 4: out = Q @ M[b] * (1/32). BM=32, grid 512, thread tile 2x4.
// ---------------------------------------------------------------------------
__global__ __launch_bounds__(256) void out_kernel(float* __restrict__ out)
{
    const int row0 = blockIdx.x * 32;
    const int b    = row0 / TT;

    __shared__ float Ms[HH][HH];
    __shared__ float QsT[HH][33];

    const int tid = threadIdx.x;
    const float* Mp = g_M + (size_t)b * HH * HH;
    for (int i = tid; i < HH * HH / 4; i += 256)
        ((float4*)&Ms[0][0])[i] = ((const float4*)Mp)[i];

#pragma unroll
    for (int it = 0; it < 2; it++) {
        int j  = tid + it * 256;
        int m  = j >> 4;
        int kk = (j & 15) * 4;
        float4 v = *(const float4*)(g_Q + (size_t)(row0 + m) * HH + kk);
        QsT[kk + 0][m] = v.x; QsT[kk + 1][m] = v.y;
        QsT[kk + 2][m] = v.z; QsT[kk + 3][m] = v.w;
    }
    __syncthreads();

    const int tx = tid % 16;
    const int ty = tid / 16;
    float acc[2][4];
#pragma unroll
    for (int i = 0; i < 2; i++)
#pragma unroll
        for (int j = 0; j < 4; j++) acc[i][j] = 0.0f;

#pragma unroll 8
    for (int k = 0; k < HH; k++) {
        float a0 = QsT[k][ty * 2 + 0];
        float a1 = QsT[k][ty * 2 + 1];
        float4 bv = *(const float4*)&Ms[k][tx * 4];
        acc[0][0] += a0 * bv.x; acc[0][1] += a0 * bv.y;
        acc[0][2] += a0 * bv.z; acc[0][3] += a0 * bv.w;
        acc[1][0] += a1 * bv.x; acc[1][1] += a1 * bv.y;
        acc[1][2] += a1 * bv.z; acc[1][3] += a1 * bv.w;
    }

    const float scale = 0.03125f;   // 1024^-0.5
#pragma unroll
    for (int i = 0; i < 2; i++) {
        float4 o;
        o.x = acc[i][0] * scale; o.y = acc[i][1] * scale;
        o.z = acc[i][2] * scale; o.w = acc[i][3] * scale;
        *(float4*)(out + (size_t)(row0 + ty * 2 + i) * HH + tx * 4) = o;
    }
}

// ---------------------------------------------------------------------------
extern "C" void kernel_launch(void* const* d_in, const int* in_sizes, int n_in,
                              void* d_out, int out_size)
{
    const float* idx = (const float*)d_in[0];
    const float* Wq  = (const float*)d_in[1];
    const float* bq  = (const float*)d_in[2];
    const float* Wk  = (const float*)d_in[3];
    const float* bk  = (const float*)d_in[4];
    const float* Wv  = (const float*)d_in[5];
    const float* bv  = (const float*)d_in[6];
    float* out = (float*)d_out;

    cudaFuncSetAttribute(qkv_mma_kernel,
                         cudaFuncAttributeMaxDynamicSharedMemorySize, SMEM_TOTAL);

    wconv_kernel<<<48, 256>>>(Wq, Wk, Wv);

    qkv_mma_kernel<<<ROWS / 128, 512, SMEM_TOTAL>>>(idx, bq, bk, bv);

    dim3 g2(BB, SPLITS);
    kv_outer_kernel<<<g2, 256>>>();

    reduce_M_kernel<<<256, 256>>>();

    out_kernel<<<ROWS / 32, 256>>>(out);
}

// round 11
// speedup vs baseline: 1.2446x; 1.2446x over previous
#include <cuda_runtime.h>
#include <cuda_fp16.h>
#include <stdint.h>

// Problem shape (fixed): idx [B=4, T=4096, E=1024], W* [E, H=64], b* [H]
// out [B, T, H] fp32.
// Math: out = (Q K^T / sqrt(E)) V == Q (K^T V) / 32  (no softmax/mask in ref)
//
// sm_103 (no 'a') PTX target: tcgen05 unavailable; tensor cores via legacy
// mma.sync.m16n8k16.f16 with fp32->fp16 2-term split on A only:
//   A = Ahi + Alo (fp16 pair, repr err ~2^-22), W single-rounded fp16 (2^-11)
//   C = Ahi*W + Alo*W     (2 passes; error dominated by W rounding ~3.7e-4)

#define BB 4
#define TT 4096
#define EE 1024
#define HH 64
#define ROWS (BB * TT)          // 16384
#define SPLITS 64
#define CHUNK (TT / SPLITS)     // 64

__device__ float g_Q[ROWS * HH];
__device__ float g_K[ROWS * HH];
__device__ float g_V[ROWS * HH];
__device__ float g_Mpart[BB * SPLITS * HH * HH];
__device__ float g_M[BB * HH * HH];
__device__ __half g_Wh[3 * HH * EE];   // W K-major fp16, row n = which*64+col

#define SW128(off) ((off) ^ (((off) >> 3) & 0x70))

__device__ __forceinline__ uint32_t s2u(const void* p) {
    return (uint32_t)__cvta_generic_to_shared(p);
}

__device__ __forceinline__ void ldsm_x4(uint32_t& r0, uint32_t& r1,
                                        uint32_t& r2, uint32_t& r3, uint32_t a) {
    asm volatile("ldmatrix.sync.aligned.m8n8.x4.shared.b16 {%0,%1,%2,%3}, [%4];"
                 : "=r"(r0), "=r"(r1), "=r"(r2), "=r"(r3) : "r"(a));
}

__device__ __forceinline__ void mma16816(float* c, const uint32_t* a,
                                         const uint32_t* b) {
    asm volatile(
        "mma.sync.aligned.m16n8k16.row.col.f32.f16.f16.f32 "
        "{%0,%1,%2,%3}, {%4,%5,%6,%7}, {%8,%9}, {%0,%1,%2,%3};"
        : "+f"(c[0]), "+f"(c[1]), "+f"(c[2]), "+f"(c[3])
        : "r"(a[0]), "r"(a[1]), "r"(a[2]), "r"(a[3]), "r"(b[0]), "r"(b[1]));
}

__device__ __forceinline__ void cp16(uint32_t dst, const void* src) {
    asm volatile("cp.async.cg.shared.global [%0], [%1], 16;"
                 :: "r"(dst), "l"(__cvta_generic_to_global(src)) : "memory");
}
__device__ __forceinline__ void cp_commit() {
    asm volatile("cp.async.commit_group;" ::: "memory");
}
__device__ __forceinline__ void cp_wait0() {
    asm volatile("cp.async.wait_group 0;" ::: "memory");
}

__device__ __forceinline__ uint32_t pack_h2(float a, float b) {
    __half2 h = __floats2half2_rn(a, b);
    return *reinterpret_cast<uint32_t*>(&h);
}

// ---------------------------------------------------------------------------
// Kernel 0: W conversion fp32 [1024,64] n-major -> g_Wh fp16 [192,1024]
// K-major. Coalesced transpose via padded smem. Grid 48 x 256.
// ---------------------------------------------------------------------------
__global__ __launch_bounds__(256) void wconv_kernel(
    const float* __restrict__ Wq, const float* __restrict__ Wk,
    const float* __restrict__ Wv)
{
    const int which = blockIdx.x >> 4;
    const int kseg  = blockIdx.x & 15;
    const int k0    = kseg * 64;
    const float* W = (which == 0) ? Wq : (which == 1) ? Wk : Wv;

    __shared__ float s[64][65];

    const int tid = threadIdx.x;
#pragma unroll
    for (int it = 0; it < 4; it++) {
        int j  = tid + it * 256;
        int r  = j >> 4;
        int c4 = (j & 15) * 4;
        float4 v = *(const float4*)(W + (size_t)(k0 + r) * HH + c4);
        s[r][c4 + 0] = v.x; s[r][c4 + 1] = v.y;
        s[r][c4 + 2] = v.z; s[r][c4 + 3] = v.w;
    }
    __syncthreads();

#pragma unroll
    for (int it = 0; it < 2; it++) {
        int id = tid + it * 256;
        int n  = id >> 3;
        int kg = (id & 7) * 8;
        uint4 hp;
        hp.x = pack_h2(s[kg + 0][n], s[kg + 1][n]);
        hp.y = pack_h2(s[kg + 2][n], s[kg + 3][n]);
        hp.z = pack_h2(s[kg + 4][n], s[kg + 5][n]);
        hp.w = pack_h2(s[kg + 6][n], s[kg + 7][n]);
        *(uint4*)(g_Wh + (size_t)(which * 64 + n) * EE + k0 + kg) = hp;
    }
}

// ---------------------------------------------------------------------------
// Kernel 1: QKV via mma.sync fp16 2-pass. 512 threads / 16 warps.
// CTA tile M=128 x N=192, K in 16 chunks of 64. Warp tile 32x48.
// A converted in-register (LDG fp32 -> fp16 hi/lo -> swizzled STS);
// W (hi only) via cp.async. Double-buffered.
// ---------------------------------------------------------------------------
#define SM_AHI 0                 // 2 x 16384
#define SM_ALO 32768             // 2 x 16384
#define SM_WH  65536             // 2 x 24576
#define SMEM_TOTAL 114688

__global__ __launch_bounds__(512, 1)
void qkv_mma_kernel(const float* __restrict__ idx,
                    const float* __restrict__ bq,
                    const float* __restrict__ bk,
                    const float* __restrict__ bv)
{
    extern __shared__ char smem[];
    const uint32_t sb = s2u(smem);
    const int tid  = threadIdx.x;
    const int lane = tid & 31;
    const int wid  = tid >> 5;
    const int wy   = wid & 3;       // M quarter: rows wy*32..+31
    const int wx   = wid >> 2;      // N group:   cols wx*48..+47
    const int row0 = blockIdx.x * 128;

    const int a_m  = lane & 15;
    const int a_k8 = (lane >> 4) * 8;
    const int b_n  = (lane & 7) + ((lane >> 4) << 3);
    const int b_k8 = ((lane >> 3) & 1) * 8;

    float acc[2][6][4];
#pragma unroll
    for (int i = 0; i < 2; i++)
#pragma unroll
        for (int j = 0; j < 6; j++)
#pragma unroll
            for (int e = 0; e < 4; e++) acc[i][j][e] = 0.0f;

    float4 st[4];   // A staging (chunk c+1)

    auto ldg_A = [&](int c) {
        const float* src = idx + (size_t)row0 * EE + c * 64;
#pragma unroll
        for (int i = 0; i < 4; i++) {
            int f4 = tid + i * 512;
            int r  = f4 >> 4;
            int cg = (f4 & 15) * 4;
            st[i] = *(const float4*)(src + (size_t)r * EE + cg);
        }
    };

    auto sts_A = [&](int buf) {
        char* aHi = smem + SM_AHI + buf * 16384;
        char* aLo = smem + SM_ALO + buf * 16384;
#pragma unroll
        for (int i = 0; i < 4; i++) {
            int f4 = tid + i * 512;
            int r  = f4 >> 4;
            int cg = (f4 & 15) * 4;
            float4 v = st[i];
            __half2 h01 = __floats2half2_rn(v.x, v.y);
            __half2 h23 = __floats2half2_rn(v.z, v.w);
            float2 f01 = __half22float2(h01);
            float2 f23 = __half22float2(h23);
            __half2 l01 = __floats2half2_rn(v.x - f01.x, v.y - f01.y);
            __half2 l23 = __floats2half2_rn(v.z - f23.x, v.w - f23.y);
            uint32_t off = SW128((uint32_t)(r * 128 + cg * 2));
            uint2 hp, lp;
            hp.x = *reinterpret_cast<uint32_t*>(&h01);
            hp.y = *reinterpret_cast<uint32_t*>(&h23);
            lp.x = *reinterpret_cast<uint32_t*>(&l01);
            lp.y = *reinterpret_cast<uint32_t*>(&l23);
            *(uint2*)(aHi + off) = hp;
            *(uint2*)(aLo + off) = lp;
        }
    };

    auto cpw = [&](int c, int buf) {
        const int k0 = c * 64;
#pragma unroll
        for (int i = 0; i < 3; i++) {
            int id = tid + i * 512;        // 0..1535
            int n  = id >> 3;              // 0..191
            int ku = id & 7;               // 16B unit
            const __half* src = g_Wh + (size_t)n * EE + k0 + ku * 8;
            uint32_t dst = sb + SM_WH + buf * 24576
                         + SW128((uint32_t)(n * 128 + ku * 16));
            cp16(dst, src);
        }
        cp_commit();
    };

    auto compute = [&](int buf) {
        const uint32_t aHiB = sb + SM_AHI + buf * 16384;
        const uint32_t aLoB = sb + SM_ALO + buf * 16384;
        const uint32_t wB   = sb + SM_WH  + buf * 24576;
#pragma unroll
        for (int ks = 0; ks < 4; ks++) {
            uint32_t aH[2][4], aL[2][4], bH[3][4];
            const uint32_t akoff = (uint32_t)((ks * 16 + a_k8) * 2);
            const uint32_t bkoff = (uint32_t)((ks * 16 + b_k8) * 2);
#pragma unroll
            for (int mi = 0; mi < 2; mi++) {
                uint32_t roff = (uint32_t)((wy * 32 + mi * 16 + a_m) * 128);
                ldsm_x4(aH[mi][0], aH[mi][1], aH[mi][2], aH[mi][3],
                        aHiB + SW128(roff + akoff));
                ldsm_x4(aL[mi][0], aL[mi][1], aL[mi][2], aL[mi][3],
                        aLoB + SW128(roff + akoff));
            }
#pragma unroll
            for (int jj = 0; jj < 3; jj++) {
                uint32_t noff = (uint32_t)((wx * 48 + jj * 16 + b_n) * 128);
                ldsm_x4(bH[jj][0], bH[jj][1], bH[jj][2], bH[jj][3],
                        wB + SW128(noff + bkoff));
            }
            // hi * W
#pragma unroll
            for (int mi = 0; mi < 2; mi++)
#pragma unroll
                for (int jj = 0; jj < 3; jj++) {
                    mma16816(acc[mi][jj * 2 + 0], aH[mi], &bH[jj][0]);
                    mma16816(acc[mi][jj * 2 + 1], aH[mi], &bH[jj][2]);
                }
            // lo * W
#pragma unroll
            for (int mi = 0; mi < 2; mi++)
#pragma unroll
                for (int jj = 0; jj < 3; jj++) {
                    mma16816(acc[mi][jj * 2 + 0], aL[mi], &bH[jj][0]);
                    mma16816(acc[mi][jj * 2 + 1], aL[mi], &bH[jj][2]);
                }
        }
    };

    ldg_A(0);
    cpw(0, 0);
    sts_A(0);
    cp_wait0();
    __syncthreads();

    for (int c = 0; c < 16; c++) {
        const int buf = c & 1;
        if (c < 15) {
            cpw(c + 1, buf ^ 1);
            ldg_A(c + 1);
        }
        compute(buf);
        if (c < 15) {
            sts_A(buf ^ 1);
            cp_wait0();
        }
        __syncthreads();
    }

    const float* const biases[3] = {bq, bk, bv};
    float* const outs[3] = {g_Q, g_K, g_V};
#pragma unroll
    for (int mi = 0; mi < 2; mi++) {
#pragma unroll
        for (int j = 0; j < 6; j++) {
            int n   = wx * 48 + j * 8 + (lane & 3) * 2;
            int t   = n >> 6;
            int col = n & 63;
            float2 bb = *(const float2*)(biases[t] + col);
            int m0 = row0 + wy * 32 + mi * 16 + (lane >> 2);
            float2 v0 = {acc[mi][j][0] + bb.x, acc[mi][j][1] + bb.y};
            float2 v1 = {acc[mi][j][2] + bb.x, acc[mi][j][3] + bb.y};
            *(float2*)(outs[t] + (size_t)m0 * HH + col) = v0;
            *(float2*)(outs[t] + (size_t)(m0 + 8) * HH + col) = v1;
        }
    }
}

// ---------------------------------------------------------------------------
// Kernel 2: partial M = K^T V over a CHUNK of T, per batch.  (unchanged)
// ---------------------------------------------------------------------------
__global__ __launch_bounds__(256) void kv_outer_kernel()
{
    const int b  = blockIdx.x;
    const int sp = blockIdx.y;
    const float* Kp = g_K + ((size_t)b * TT + (size_t)sp * CHUNK) * HH;
    const float* Vp = g_V + ((size_t)b * TT + (size_t)sp * CHUNK) * HH;

    __shared__ float Ks[CHUNK][HH];
    __shared__ float Vs[CHUNK][HH];

    const int tid = threadIdx.x;
    for (int i = tid; i < CHUNK * HH / 4; i += 256) {
        ((float4*)&Ks[0][0])[i] = ((const float4*)Kp)[i];
        ((float4*)&Vs[0][0])[i] = ((const float4*)Vp)[i];
    }
    __syncthreads();

    const int tx = tid % 16;
    const int ty = tid / 16;
    float acc[4][4];
#pragma unroll
    for (int i = 0; i < 4; i++)
#pragma unroll
        for (int j = 0; j < 4; j++) acc[i][j] = 0.0f;

    for (int s = 0; s < CHUNK; s++) {
        float4 kv = *(const float4*)&Ks[s][ty * 4];
        float4 vv = *(const float4*)&Vs[s][tx * 4];
        float ka[4] = {kv.x, kv.y, kv.z, kv.w};
        float va[4] = {vv.x, vv.y, vv.z, vv.w};
#pragma unroll
        for (int i = 0; i < 4; i++)
#pragma unroll
            for (int j = 0; j < 4; j++) acc[i][j] += ka[i] * va[j];
    }

    float* outp = g_Mpart + ((size_t)(b * SPLITS + sp)) * HH * HH;
#pragma unroll
    for (int i = 0; i < 4; i++) {
        float4 o = {acc[i][0], acc[i][1], acc[i][2], acc[i][3]};
        *(float4*)(outp + (size_t)(ty * 4 + i) * HH + tx * 4) = o;
    }
}

// ---------------------------------------------------------------------------
// Kernel 3: reduce partials -> M[b]. Grid 256 (4b x 64 segs), 256 thr.
// ---------------------------------------------------------------------------
__global__ __launch_bounds__(256) void reduce_M_kernel()
{
    const int b    = blockIdx.x >> 6;
    const int seg  = blockIdx.x & 63;
    const int tcol = threadIdx.x & 15;
    const int pg   = threadIdx.x >> 4;

    const float4* base = (const float4*)g_Mpart
        + (size_t)b * SPLITS * 1024 + (size_t)(pg * 4) * 1024 + seg * 16 + tcol;

    float4 s = {0.f, 0.f, 0.f, 0.f};
#pragma unroll
    for (int p = 0; p < 4; p++) {
        float4 v = base[(size_t)p * 1024];
        s.x += v.x; s.y += v.y; s.z += v.z; s.w += v.w;
    }

    __shared__ float4 red[16][16];
    red[pg][tcol] = s;
    __syncthreads();
    if (pg == 0) {
        float4 o = red[0][tcol];
#pragma unroll
        for (int g = 1; g < 16; g++) {
            float4 v = red[g][tcol];
            o.x += v.x; o.y += v.y; o.z += v.z; o.w += v.w;
        }
        ((float4*)g_M)[(size_t)b * 1024 + seg * 16 + tcol] = o;
    }
}

// ---------------------------------------------------------------------------
// Kernel 4: out = Q @ M[b] * (1/32). BM=32, grid 512, thread tile 2x4.
// ---------------------------------------------------------------------------
__global__ __launch_bounds__(256) void out_kernel(float* __restrict__ out)
{
    const int row0 = blockIdx.x * 32;
    const int b    = row0 / TT;

    __shared__ float Ms[HH][HH];
    __shared__ float QsT[HH][33];

    const int tid = threadIdx.x;
    const float* Mp = g_M + (size_t)b * HH * HH;
    for (int i = tid; i < HH * HH / 4; i += 256)
        ((float4*)&Ms[0][0])[i] = ((const float4*)Mp)[i];

#pragma unroll
    for (int it = 0; it < 2; it++) {
        int j  = tid + it * 256;
        int m  = j >> 4;
        int kk = (j & 15) * 4;
        float4 v = *(const float4*)(g_Q + (size_t)(row0 + m) * HH + kk);
        QsT[kk + 0][m] = v.x; QsT[kk + 1][m] = v.y;
        QsT[kk + 2][m] = v.z; QsT[kk + 3][m] = v.w;
    }
    __syncthreads();

    const int tx = tid % 16;
    const int ty = tid / 16;
    float acc[2][4];
#pragma unroll
    for (int i = 0; i < 2; i++)
#pragma unroll
        for (int j = 0; j < 4; j++) acc[i][j] = 0.0f;

#pragma unroll 8
    for (int k = 0; k < HH; k++) {
        float a0 = QsT[k][ty * 2 + 0];
        float a1 = QsT[k][ty * 2 + 1];
        float4 bv = *(const float4*)&Ms[k][tx * 4];
        acc[0][0] += a0 * bv.x; acc[0][1] += a0 * bv.y;
        acc[0][2] += a0 * bv.z; acc[0][3] += a0 * bv.w;
        acc[1][0] += a1 * bv.x; acc[1][1] += a1 * bv.y;
        acc[1][2] += a1 * bv.z; acc[1][3] += a1 * bv.w;
    }

    const float scale = 0.03125f;   // 1024^-0.5
#pragma unroll
    for (int i = 0; i < 2; i++) {
        float4 o;
        o.x = acc[i][0] * scale; o.y = acc[i][1] * scale;
        o.z = acc[i][2] * scale; o.w = acc[i][3] * scale;
        *(float4*)(out + (size_t)(row0 + ty * 2 + i) * HH + tx * 4) = o;
    }
}

// ---------------------------------------------------------------------------
extern "C" void kernel_launch(void* const* d_in, const int* in_sizes, int n_in,
                              void* d_out, int out_size)
{
    const float* idx = (const float*)d_in[0];
    const float* Wq  = (const float*)d_in[1];
    const float* bq  = (const float*)d_in[2];
    const float* Wk  = (const float*)d_in[3];
    const float* bk  = (const float*)d_in[4];
    const float* Wv  = (const float*)d_in[5];
    const float* bv  = (const float*)d_in[6];
    float* out = (float*)d_out;

    cudaFuncSetAttribute(qkv_mma_kernel,
                         cudaFuncAttributeMaxDynamicSharedMemorySize, SMEM_TOTAL);

    wconv_kernel<<<48, 256>>>(Wq, Wk, Wv);

    qkv_mma_kernel<<<ROWS / 128, 512, SMEM_TOTAL>>>(idx, bq, bk, bv);

    dim3 g2(BB, SPLITS);
    kv_outer_kernel<<<g2, 256>>>();

    reduce_M_kernel<<<256, 256>>>();

    out_kernel<<<ROWS / 32, 256>>>(out);
}